// round 15
// baseline (speedup 1.0000x reference)
#include <cuda_runtime.h>

#define NATOMS 512
#define BATCH  32
#define NN     (NATOMS * NATOMS)
#define NT     16
#define NTILES (NT * (NT + 1) / 2)   // 136

typedef unsigned long long u64;

struct F3 { float x, y, z; };

__device__ __forceinline__ F3 f3sub(float4 a, float4 b) { return {a.x - b.x, a.y - b.y, a.z - b.z}; }
__device__ __forceinline__ F3 f3cross(F3 a, F3 b) {
    return {a.y * b.z - a.z * b.y,
            a.z * b.x - a.x * b.z,
            a.x * b.y - a.y * b.x};
}
__device__ __forceinline__ float f3dot(F3 a, F3 b) { return a.x * b.x + a.y * b.y + a.z * b.z; }

__device__ __forceinline__ float rsqrt_a(float x) {
    float r; asm("rsqrt.approx.f32 %0, %1;" : "=f"(r) : "f"(x)); return r;
}
__device__ __forceinline__ float sqrt_a(float x) {
    float r; asm("sqrt.approx.f32 %0, %1;" : "=f"(r) : "f"(x)); return r;
}

// ---- packed f32x2 helpers (non-volatile: CSE-able) ----
__device__ __forceinline__ u64 pk2(float lo, float hi) {
    u64 r; asm("mov.b64 %0, {%1, %2};" : "=l"(r) : "f"(lo), "f"(hi)); return r;
}
__device__ __forceinline__ void upk2(u64 v, float& lo, float& hi) {
    asm("mov.b64 {%0, %1}, %2;" : "=f"(lo), "=f"(hi) : "l"(v));
}
__device__ __forceinline__ u64 fma2(u64 a, u64 b, u64 c) {
    u64 d; asm("fma.rn.f32x2 %0, %1, %2, %3;" : "=l"(d) : "l"(a), "l"(b), "l"(c)); return d;
}

// Paired scaled asin: returns asin(x)/(2*pi). A&S 4.4.46 coefficients and the
// pi/2 constants pre-multiplied by 1/(2*pi)  (|err| <= 2e-8 / 2pi).
__device__ __forceinline__ void asin2pi_fast(float xa, float xb, float& ra, float& rb) {
    float ta = fminf(fabsf(xa), 1.0f);
    float tb = fminf(fabsf(xb), 1.0f);
    float sa = 1.0f - ta;
    float sb = 1.0f - tb;

    u64 t2 = pk2(ta, tb);
    u64 p  = pk2(-2.0092277e-4f, -2.0092277e-4f);
    p = fma2(p, t2, pk2( 1.0615793e-3f,  1.0615793e-3f));
    p = fma2(p, t2, pk2(-2.7196690e-3f, -2.7196690e-3f));
    p = fma2(p, t2, pk2( 4.9166075e-3f,  4.9166075e-3f));
    p = fma2(p, t2, pk2(-7.9855286e-3f, -7.9855286e-3f));
    p = fma2(p, t2, pk2( 1.4161419e-2f,  1.4161419e-2f));
    p = fma2(p, t2, pk2(-3.4156516e-2f, -3.4156516e-2f));
    p = fma2(p, t2, pk2( 2.4999999e-1f,  2.4999999e-1f));

    float pa, pb;
    upk2(p, pa, pb);
    float qa = fmaf(sqrt_a(sa), -pa, 0.25f);
    float qb = fmaf(sqrt_a(sb), -pb, 0.25f);
    ra = copysignf(qa, xa);
    rb = copysignf(qb, xb);
}

// One cell using g = x[j+1]-x[j]:
//   u0 = e0 x g, u2 = g x e2, u3 = e2 x e0, u1 = u0+u2-u3 (exact; never built).
// Gram expansion supplies all u1-dots:
//   n1  = n0+n2+n3 + 2(d02 - d03 - d23)
//   d01 = n0 + d02 - d03
//   d12 = n2 + d02 - d23
// Carry from cell (i-1,j): e0 = prev e2; u0reg = prev u2 == -(true u0);
// n0 = prev n2; r0 = prev r2. Carried d02r/d03r/dsv flip sign vs true;
// the combinations below compensate exactly.
template<bool FIRST>
__device__ __forceinline__ float cell_wr(
    F3 e0in, float4 P1, F3 g, float4 P2,
    F3& ce2, F3& cu2, float& cn2, float& cr2)
{
    F3 e0;
    if (FIRST) e0 = e0in;
    else       e0 = ce2;
    F3 e2 = f3sub(P2, P1);

    F3 u0; float n0, r0;
    if (FIRST) {
        u0 = f3cross(e0, g);
        n0 = f3dot(u0, u0);
        r0 = rsqrt_a(n0);
    } else {
        u0 = cu2;            // == -(true u0)
        n0 = cn2;
        r0 = cr2;
    }

    F3 u2 = f3cross(g, e2);
    F3 u3 = f3cross(e2, e0);

    float n2   = f3dot(u2, u2);
    float n3   = f3dot(u3, u3);
    float d23  = f3dot(u2, u3);     // true (u2, u3 both fresh)
    float d02r = f3dot(u0, u2);     // = +-d02
    float d03r = f3dot(u0, u3);     // = +-d03
    float dsv  = f3dot(u0, e2);

    float n1, d01, d12, d30;
    if (FIRST) {
        n1  = fmaf(2.0f, (d02r - d03r) - d23, (n0 + n2) + n3);
        d01 = (n0 + d02r) - d03r;
        d12 = (n2 + d02r) - d23;
        d30 = d03r;
    } else {
        n1  = fmaf(2.0f, (d03r - d02r) - d23, (n0 + n2) + n3);
        d01 = (n0 - d02r) + d03r;
        d12 = (n2 - d02r) - d23;
        d30 = -d03r;
    }

    float r1 = rsqrt_a(n1);
    float r2 = rsqrt_a(n2);
    float r3 = rsqrt_a(n3);

    float t01 = d01 * (r0 * r1);
    float t12 = d12 * (r1 * r2);
    float t23 = d23 * (r2 * r3);
    float t30 = d30 * (r3 * r0);

    float a01, a12, a23, a30;
    asin2pi_fast(t01, t12, a01, a12);
    asin2pi_fast(t23, t30, a23, a30);
    float om = (a01 + a12) + (a23 + a30);   // already scaled by 1/2pi

    // true sv = -(u0_true . e2); carried u0reg is already negated.
    unsigned smask;
    if (FIRST)
        smask = (__float_as_uint(dsv) ^ 0x80000000u) & 0x80000000u;
    else
        smask = __float_as_uint(dsv) & 0x80000000u;
    float wr = __uint_as_float(__float_as_uint(om) ^ smask);

    ce2 = e2; cu2 = u2; cn2 = n2; cr2 = r2;
    return wr;
}

// Segment set: {(i,j): 0<=i<=509, i+2<=j<=510}. Final scatter state:
// every (i,j) owns out[i+1][j+1] (+mirror); i==0 also keeps out[0][j] (+mirror).
// Never-written cells (|r-c|<=1 band, (0,511),(511,0)) zeroed by diagonal tiles.
// 64 threads/block: lane tx = j offset (0..31), warp ty (0..1) covers 16
// consecutive i per thread. Stores issue in-loop (no register wr buffer).
__global__ __launch_bounds__(64, 24) void writhe_tile_kernel(
    const float* __restrict__ x,
    float*       __restrict__ out)
{
    __shared__ float4 si[33];
    __shared__ float4 sj4[33];
    __shared__ float  smwr[32][33];

    // Closed-form decode of k -> (ti, tj), row ti has 16-ti entries.
    const int k = blockIdx.x;
    int ti = (int)((33.0f - sqrtf((float)(1089 - 8 * k))) * 0.5f);
    if (k < ti * (33 - ti) / 2) ti--;
    else if (k >= (ti + 1) * (32 - ti) / 2) ti++;
    const int tj = ti + (k - ti * (33 - ti) / 2);
    const int i0 = ti * 32, j0 = tj * 32;
    const bool fastTile = (ti >= 1) && (tj >= ti + 2) && (tj <= 14);

    const int b = blockIdx.y;
    const float* xb = x + (size_t)b * (NATOMS * 3);
    float* ob = out + (size_t)b * NN;

    const int tx = threadIdx.x & 31;
    const int ty = threadIdx.x >> 5;    // 0..1

    for (int t = threadIdx.x; t < 66; t += 64) {
        int local = (t < 33) ? t : t - 33;
        int c = min(((t < 33) ? i0 : j0) + local, NATOMS - 1);
        float4 v = make_float4(xb[3 * c], xb[3 * c + 1], xb[3 * c + 2], 0.f);
        if (t < 33) si[local] = v; else sj4[local] = v;
    }
    if (ty == 1 && ti == tj) {
        int r = i0 + tx;
        ob[r * 513] = 0.f;
        if (r < NATOMS - 1) { ob[r * 513 + 1] = 0.f; ob[r * 513 + 512] = 0.f; }
        if (ti == 0 && tx == 0) { ob[NATOMS - 1] = 0.f; ob[(NATOMS - 1) * NATOMS] = 0.f; }
    }
    __syncthreads();

    const int j = j0 + tx;
    const float4 P2 = sj4[tx];
    const float4 P3 = sj4[tx + 1];
    const F3 g = f3sub(P3, P2);          // x[j+1]-x[j], per-thread constant
    const int ibase = 16 * ty;           // 16 consecutive i per thread

    F3 ce2, cu2;
    float cn2, cr2;

    float* orow = ob + (size_t)(i0 + ibase + 1) * NATOMS + (j + 1);

    // Cell 0 peeled: only place si[ibase] (P0) is needed.
    {
        F3 e00 = f3sub(P2, si[ibase]);
        float wr = cell_wr<true>(e00, si[ibase + 1], g, P2, ce2, cu2, cn2, cr2);
        smwr[ibase][tx] = wr;
        if (fastTile) {
            orow[0] = wr;
        } else {
            const int i = i0 + ibase;
            if ((j >= i + 2) && (i <= NATOMS - 3) && (j <= NATOMS - 2)) {
                ob[(i + 1) * NATOMS + (j + 1)] = wr;
                if (i == 0) { ob[j] = wr; ob[j * NATOMS] = wr; }
            }
        }
    }
    #pragma unroll
    for (int kk = 1; kk < 16; kk++) {
        const int ii = ibase + kk;
        float wr = cell_wr<false>(F3{0.f, 0.f, 0.f}, si[ii + 1], g, P2, ce2, cu2, cn2, cr2);
        smwr[ii][tx] = wr;
        if (fastTile) {
            orow[kk * NATOMS] = wr;
        } else {
            const int i = i0 + ii;
            if ((j >= i + 2) && (i <= NATOMS - 3) && (j <= NATOMS - 2)) {
                ob[(i + 1) * NATOMS + (j + 1)] = wr;
                if (i == 0) { ob[j] = wr; ob[j * NATOMS] = wr; }
            }
        }
    }
    __syncthreads();

    // Mirror: coalesced out[j+1][i+1] via transposed smem reads (stride 33).
    if (fastTile) {
        float* ocol = ob + (size_t)(j0 + ibase + 1) * NATOMS + (i0 + tx + 1);
        #pragma unroll
        for (int kk = 0; kk < 16; kk++)
            ocol[kk * NATOMS] = smwr[tx][ibase + kk];
    } else {
        #pragma unroll
        for (int kk = 0; kk < 16; kk++) {
            const int jj = ibase + kk;
            const int jm = j0 + jj;
            const int im = i0 + tx;
            float v = smwr[tx][jj];
            bool valid = (jm >= im + 2) && (im <= NATOMS - 3) && (jm <= NATOMS - 2);
            if (valid)
                ob[(jm + 1) * NATOMS + (im + 1)] = v;
        }
    }
}

extern "C" void kernel_launch(void* const* d_in, const int* in_sizes, int n_in,
                              void* d_out, int out_size)
{
    int xi = (in_sizes[0] == BATCH * NATOMS * 3) ? 0 : 1;
    const float* x   = (const float*)d_in[xi];
    float*       out = (float*)d_out;

    dim3 grid(NTILES, BATCH);
    writhe_tile_kernel<<<grid, 64>>>(x, out);
}

// round 16
// speedup vs baseline: 1.1465x; 1.1465x over previous
#include <cuda_runtime.h>

#define NATOMS 512
#define BATCH  32
#define NN     (NATOMS * NATOMS)
#define NT     16
#define NTILES (NT * (NT + 1) / 2)   // 136

typedef unsigned long long u64;

struct F3 { float x, y, z; };

__device__ __forceinline__ F3 f3sub(float4 a, float4 b) { return {a.x - b.x, a.y - b.y, a.z - b.z}; }
__device__ __forceinline__ F3 f3cross(F3 a, F3 b) {
    return {a.y * b.z - a.z * b.y,
            a.z * b.x - a.x * b.z,
            a.x * b.y - a.y * b.x};
}
__device__ __forceinline__ float f3dot(F3 a, F3 b) { return a.x * b.x + a.y * b.y + a.z * b.z; }

__device__ __forceinline__ float rsqrt_a(float x) {
    float r; asm("rsqrt.approx.f32 %0, %1;" : "=f"(r) : "f"(x)); return r;
}
__device__ __forceinline__ float sqrt_a(float x) {
    float r; asm("sqrt.approx.f32 %0, %1;" : "=f"(r) : "f"(x)); return r;
}

// ---- packed f32x2 helpers (non-volatile: CSE-able) ----
__device__ __forceinline__ u64 pk2(float lo, float hi) {
    u64 r; asm("mov.b64 %0, {%1, %2};" : "=l"(r) : "f"(lo), "f"(hi)); return r;
}
__device__ __forceinline__ void upk2(u64 v, float& lo, float& hi) {
    asm("mov.b64 {%0, %1}, %2;" : "=f"(lo), "=f"(hi) : "l"(v));
}
__device__ __forceinline__ u64 fma2(u64 a, u64 b, u64 c) {
    u64 d; asm("fma.rn.f32x2 %0, %1, %2, %3;" : "=l"(d) : "l"(a), "l"(b), "l"(c)); return d;
}

// Paired scaled asin: returns asin(x)/(2*pi). A&S 4.4.46 coefficients and the
// pi/2 constants pre-multiplied by 1/(2*pi)  (|err| <= 2e-8 / 2pi).
__device__ __forceinline__ void asin2pi_fast(float xa, float xb, float& ra, float& rb) {
    float ta = fminf(fabsf(xa), 1.0f);
    float tb = fminf(fabsf(xb), 1.0f);
    float sa = 1.0f - ta;
    float sb = 1.0f - tb;

    u64 t2 = pk2(ta, tb);
    u64 p  = pk2(-2.0092277e-4f, -2.0092277e-4f);
    p = fma2(p, t2, pk2( 1.0615793e-3f,  1.0615793e-3f));
    p = fma2(p, t2, pk2(-2.7196690e-3f, -2.7196690e-3f));
    p = fma2(p, t2, pk2( 4.9166075e-3f,  4.9166075e-3f));
    p = fma2(p, t2, pk2(-7.9855286e-3f, -7.9855286e-3f));
    p = fma2(p, t2, pk2( 1.4161419e-2f,  1.4161419e-2f));
    p = fma2(p, t2, pk2(-3.4156516e-2f, -3.4156516e-2f));
    p = fma2(p, t2, pk2( 2.4999999e-1f,  2.4999999e-1f));

    float pa, pb;
    upk2(p, pa, pb);
    float qa = fmaf(sqrt_a(sa), -pa, 0.25f);
    float qb = fmaf(sqrt_a(sb), -pb, 0.25f);
    ra = copysignf(qa, xa);
    rb = copysignf(qb, xb);
}

// One cell using g = x[j+1]-x[j]:
//   u0 = e0 x g, u2 = g x e2, u3 = e2 x e0, u1 = u0+u2-u3 (exact; never built).
// Gram expansion supplies all u1-dots:
//   n1  = n0+n2+n3 + 2(d02 - d03 - d23)
//   d01 = n0 + d02 - d03
//   d12 = n2 + d02 - d23
// Carry from cell (i-1,j): e0 = prev e2; u0reg = prev u2 == -(true u0);
// n0 = prev n2; r0 = prev r2. Carried d02r/d03r/dsv flip sign vs true;
// the combinations below compensate exactly.
template<bool FIRST>
__device__ __forceinline__ float cell_wr(
    F3 e0in, float4 P1, F3 g, float4 P2,
    F3& ce2, F3& cu2, float& cn2, float& cr2)
{
    F3 e0;
    if (FIRST) e0 = e0in;
    else       e0 = ce2;
    F3 e2 = f3sub(P2, P1);

    F3 u0; float n0, r0;
    if (FIRST) {
        u0 = f3cross(e0, g);
        n0 = f3dot(u0, u0);
        r0 = rsqrt_a(n0);
    } else {
        u0 = cu2;            // == -(true u0)
        n0 = cn2;
        r0 = cr2;
    }

    F3 u2 = f3cross(g, e2);
    F3 u3 = f3cross(e2, e0);

    float n2   = f3dot(u2, u2);
    float n3   = f3dot(u3, u3);
    float d23  = f3dot(u2, u3);     // true (u2, u3 both fresh)
    float d02r = f3dot(u0, u2);     // = +-d02
    float d03r = f3dot(u0, u3);     // = +-d03
    float dsv  = f3dot(u0, e2);

    float n1, d01, d12, d30;
    if (FIRST) {
        n1  = fmaf(2.0f, (d02r - d03r) - d23, (n0 + n2) + n3);
        d01 = (n0 + d02r) - d03r;
        d12 = (n2 + d02r) - d23;
        d30 = d03r;
    } else {
        n1  = fmaf(2.0f, (d03r - d02r) - d23, (n0 + n2) + n3);
        d01 = (n0 - d02r) + d03r;
        d12 = (n2 - d02r) - d23;
        d30 = -d03r;
    }

    float r1 = rsqrt_a(n1);
    float r2 = rsqrt_a(n2);
    float r3 = rsqrt_a(n3);

    float t01 = d01 * (r0 * r1);
    float t12 = d12 * (r1 * r2);
    float t23 = d23 * (r2 * r3);
    float t30 = d30 * (r3 * r0);

    float a01, a12, a23, a30;
    asin2pi_fast(t01, t12, a01, a12);
    asin2pi_fast(t23, t30, a23, a30);
    float om = (a01 + a12) + (a23 + a30);   // already scaled by 1/2pi

    // true sv = -(u0_true . e2); carried u0reg is already negated.
    unsigned smask;
    if (FIRST)
        smask = (__float_as_uint(dsv) ^ 0x80000000u) & 0x80000000u;
    else
        smask = __float_as_uint(dsv) & 0x80000000u;
    float wr = __uint_as_float(__float_as_uint(om) ^ smask);

    ce2 = e2; cu2 = u2; cn2 = n2; cr2 = r2;
    return wr;
}

// Segment set: {(i,j): 0<=i<=509, i+2<=j<=510}. Final scatter state:
// every (i,j) owns out[i+1][j+1] (+mirror); i==0 also keeps out[0][j] (+mirror).
// Never-written cells (|r-c|<=1 band, (0,511),(511,0)) zeroed by diagonal tiles.
// 128 threads/block: lane tx = j offset, warp ty (0..3) covers 8 consecutive i.
__global__ __launch_bounds__(128, 12) void writhe_tile_kernel(
    const float* __restrict__ x,
    float*       __restrict__ out)
{
    __shared__ float4 si[33];
    __shared__ float4 sj4[33];
    __shared__ float  smwr[32][33];

    // Closed-form decode of k -> (ti, tj), row ti has 16-ti entries.
    const int k = blockIdx.x;
    int ti = (int)((33.0f - sqrtf((float)(1089 - 8 * k))) * 0.5f);
    if (k < ti * (33 - ti) / 2) ti--;
    else if (k >= (ti + 1) * (32 - ti) / 2) ti++;
    const int tj = ti + (k - ti * (33 - ti) / 2);
    const int i0 = ti * 32, j0 = tj * 32;
    const bool fastTile = (ti >= 1) && (tj >= ti + 2) && (tj <= 14);
    const bool row0 = (ti == 0);          // only these tiles can have i==0 specials

    const int b = blockIdx.y;
    const float* xb = x + (size_t)b * (NATOMS * 3);
    float* ob = out + (size_t)b * NN;

    const int tx = threadIdx.x & 31;
    const int ty = threadIdx.x >> 5;    // 0..3

    {
        int t = threadIdx.x;
        if (t < 66) {
            int local = (t < 33) ? t : t - 33;
            int c = min(((t < 33) ? i0 : j0) + local, NATOMS - 1);
            float4 v = make_float4(xb[3 * c], xb[3 * c + 1], xb[3 * c + 2], 0.f);
            if (t < 33) si[local] = v; else sj4[local] = v;
        }
    }
    if (ty == 1 && ti == tj) {
        int r = i0 + tx;
        ob[r * 513] = 0.f;
        if (r < NATOMS - 1) { ob[r * 513 + 1] = 0.f; ob[r * 513 + 512] = 0.f; }
        if (ti == 0 && tx == 0) { ob[NATOMS - 1] = 0.f; ob[(NATOMS - 1) * NATOMS] = 0.f; }
    }
    __syncthreads();

    const int j = j0 + tx;
    const float4 P2 = sj4[tx];
    const float4 P3 = sj4[tx + 1];
    const F3 g = f3sub(P3, P2);          // x[j+1]-x[j], per-thread constant
    const int ibase = 8 * ty;            // 8 consecutive i per thread

    F3 ce2, cu2;
    float cn2, cr2;
    float wrv[8];

    // Cell 0 peeled: only place si[ibase] (P0) is needed.
    {
        F3 e00 = f3sub(P2, si[ibase]);
        wrv[0] = cell_wr<true>(e00, si[ibase + 1], g, P2, ce2, cu2, cn2, cr2);
        smwr[ibase][tx] = wrv[0];
    }
    #pragma unroll
    for (int kk = 1; kk < 8; kk++) {
        const int ii = ibase + kk;
        wrv[kk] = cell_wr<false>(F3{0.f, 0.f, 0.f}, si[ii + 1], g, P2, ce2, cu2, cn2, cr2);
        smwr[ii][tx] = wrv[kk];
    }

    if (fastTile) {
        float* orow = ob + (size_t)(i0 + ibase + 1) * NATOMS + (j + 1);
        #pragma unroll
        for (int kk = 0; kk < 8; kk++)
            orow[kk * NATOMS] = wrv[kk];
    } else {
        #pragma unroll
        for (int kk = 0; kk < 8; kk++) {
            const int i = i0 + ibase + kk;
            bool valid = (j >= i + 2) && (i <= NATOMS - 3) && (j <= NATOMS - 2);
            if (valid) {
                ob[(i + 1) * NATOMS + (j + 1)] = wrv[kk];
                if (row0 && i == 0) {
                    ob[j] = wrv[kk];              // (0, j) first-scatter survivor
                    ob[j * NATOMS] = wrv[kk];     // (j, 0)
                }
            }
        }
    }
    __syncthreads();

    // Mirror: coalesced out[j+1][i+1] via transposed smem reads (stride 33).
    if (fastTile) {
        float* ocol = ob + (size_t)(j0 + ibase + 1) * NATOMS + (i0 + tx + 1);
        #pragma unroll
        for (int kk = 0; kk < 8; kk++)
            ocol[kk * NATOMS] = smwr[tx][ibase + kk];
    } else {
        #pragma unroll
        for (int kk = 0; kk < 8; kk++) {
            const int jj = ibase + kk;
            const int jm = j0 + jj;
            const int im = i0 + tx;
            float v = smwr[tx][jj];
            bool valid = (jm >= im + 2) && (im <= NATOMS - 3) && (jm <= NATOMS - 2);
            if (valid)
                ob[(jm + 1) * NATOMS + (im + 1)] = v;
        }
    }
}

extern "C" void kernel_launch(void* const* d_in, const int* in_sizes, int n_in,
                              void* d_out, int out_size)
{
    int xi = (in_sizes[0] == BATCH * NATOMS * 3) ? 0 : 1;
    const float* x   = (const float*)d_in[xi];
    float*       out = (float*)d_out;

    dim3 grid(NTILES, BATCH);
    writhe_tile_kernel<<<grid, 128>>>(x, out);
}